// round 8
// baseline (speedup 1.0000x reference)
#include <cuda_runtime.h>

// Fused beam reorder + suffix append for KV cache.
// Shapes: L=8, G=128, NH=8, T=128, HD=64, fp32.
//   out_k[l,g,h,t,:] = (t==pos) ? k_new[l,g,h,0,:] : k_buf[l,beam[g],h,t,:]
//   out_v analogous. Output = [k ; v] concatenated.
//
// float4 (16B) units: NEL4 = 2^24 per buffer; beam stride = 2^14.
//   t=(j>>4)&127; g=(j>>14)&127; gather src = j + (beam[g]-g)<<14
//   append src = ((j>>11)<<4)|(j&15)   ({k,v}_new is [L,G,NH,1,HD])
//
// R8: software-pipelined grid-stride. Each block processes ITER chunks of
// 1024 float4 with a register double buffer: loads for chunk i+1 are issued
// BEFORE the stores of chunk i, so every warp keeps a continuous read stream
// through store-drain phases (batch-phase kernels go read-silent while
// draining stores). Traffic unchanged (~836 MB compulsory); this targets the
// last ~2% of DRAM utilization (82% -> ~85%).

static constexpr unsigned NEL4   = 1u << 24;     // float4s per buffer
static constexpr unsigned TOTAL  = 1u << 25;     // k + v
static constexpr int      ILP    = 4;
static constexpr int      THREADS = 256;
static constexpr unsigned CHUNK  = THREADS * ILP;        // 1024 float4
static constexpr unsigned NCHUNK = TOTAL / CHUNK;        // 32768
static constexpr unsigned GRID   = 2048;
static constexpr unsigned ITER   = NCHUNK / GRID;        // 16

__device__ __forceinline__ void load_chunk(unsigned chunk,
                                           const float4* __restrict__ kb,
                                           const float4* __restrict__ vb,
                                           const float4* __restrict__ kn,
                                           const float4* __restrict__ vn,
                                           const int*    __restrict__ beam,
                                           int pos, float4 r[ILP])
{
    const unsigned base  = chunk * CHUNK;                 // 1024-aligned
    const bool is_v      = base >= NEL4;                  // uniform
    const unsigned jbase = base & (NEL4 - 1);
    const unsigned g     = (jbase >> 14) & 127;           // uniform
    const unsigned delta = ((unsigned)(beam[g] - (int)g)) << 14;

    const float4* __restrict__ buf  = is_v ? vb : kb;
    const float4* __restrict__ nbuf = is_v ? vn : kn;

    #pragma unroll
    for (int k = 0; k < ILP; k++) {
        const unsigned j = jbase + threadIdx.x + (unsigned)k * THREADS;
        const unsigned t = (j >> 4) & 127;
        const bool app = (t == (unsigned)pos);
        const unsigned sidx = app ? (((j >> 11) << 4) | (j & 15))
                                  : (j + delta);
        const float4* __restrict__ src = app ? nbuf : buf;
        r[k] = __ldg(src + sidx);
    }
}

__global__ void __launch_bounds__(THREADS)
beam_reorder_append_kernel(const float4* __restrict__ kb,
                           const float4* __restrict__ vb,
                           const float4* __restrict__ kn,
                           const float4* __restrict__ vn,
                           const int*    __restrict__ beam,
                           const int*    __restrict__ posp,
                           float4*       __restrict__ out)
{
    const int pos = *posp;                                // L1-hit, uniform

    unsigned c = blockIdx.x;                              // current chunk
    float4 rA[ILP], rB[ILP];

    load_chunk(c, kb, vb, kn, vn, beam, pos, rA);         // prologue

    #pragma unroll 1
    for (unsigned it = 0; it + 1 < ITER; it++) {
        const unsigned cn = c + GRID;
        // Issue next chunk's 4 loads BEFORE draining current stores.
        load_chunk(cn, kb, vb, kn, vn, beam, pos, rB);

        const unsigned obase = c * CHUNK + threadIdx.x;
        #pragma unroll
        for (int k = 0; k < ILP; k++)
            __stcs(out + obase + (unsigned)k * THREADS, rA[k]);

        #pragma unroll
        for (int k = 0; k < ILP; k++) rA[k] = rB[k];
        c = cn;
    }

    // epilogue: store last chunk
    const unsigned obase = c * CHUNK + threadIdx.x;
    #pragma unroll
    for (int k = 0; k < ILP; k++)
        __stcs(out + obase + (unsigned)k * THREADS, rA[k]);
}

extern "C" void kernel_launch(void* const* d_in, const int* in_sizes, int n_in,
                              void* d_out, int out_size)
{
    const float4* kb   = (const float4*)d_in[0];  // k_buf  [L,G,NH,T,HD] fp32
    const float4* vb   = (const float4*)d_in[1];  // v_buf
    const float4* kn   = (const float4*)d_in[2];  // k_new  [L,G,NH,1,HD]
    const float4* vn   = (const float4*)d_in[3];  // v_new
    const int*    beam = (const int*)d_in[4];     // new_beam_idx [G]
    const int*    posp = (const int*)d_in[5];     // pos (scalar, device-side)
    float4*       out  = (float4*)d_out;          // [2,L,G,NH,T,HD] fp32

    beam_reorder_append_kernel<<<GRID, THREADS>>>(
        kb, vb, kn, vn, beam, posp, out);
}

// round 9
// speedup vs baseline: 1.1663x; 1.1663x over previous
#include <cuda_runtime.h>
#include <cstdint>

// Fused beam reorder + suffix append for KV cache.   [R4 structure + 256-bit ops]
// Shapes: L=8, G=128, NH=8, T=128, HD=64, fp32.
//   out_k[l,g,h,t,:] = (t==pos) ? k_new[l,g,h,0,:] : k_buf[l,beam[g],h,t,:]
//   out_v analogous. Output = [k ; v] concatenated.
//
// float4 (16B) units: NEL4 = 2^24 per buffer; beam stride = 2^14.
//   t=(j>>4)&127; g=(j>>14)&127; gather src = j + (beam[g]-g)<<14
//   append src = ((j>>11)<<4)|(j&15)   ({k,v}_new is [L,G,NH,1,HD])
//
// Evidence so far: compulsory traffic ≈ 836 MB; 6.51-6.55 TB/s ceiling across
// ILP/cache/order variants; full-grid batch-phase launch is required for L2
// dedup of duplicate beams (persistent pipeline broke dedup, +120MB, R8).
// This round: same R4 shape, but sm_100+ 256-bit ld/st (v8.b32) — each v8
// covers float4 pair (j, j+1), j even: same t, and gather/append sources stay
// 32B-aligned (delta and sidx both even). Halves LSU instruction count.

static constexpr unsigned NEL4   = 1u << 24;     // float4s per buffer
static constexpr unsigned TOTAL  = 1u << 25;     // k + v
static constexpr int      THREADS = 256;
static constexpr unsigned CHUNK  = 1024;         // float4 per block (1024-aligned)
static constexpr int      V8_PER_THREAD = 2;     // 2 x 32B = 64B/thread

__device__ __forceinline__ void ldg256(const float4* p, uint32_t r[8]) {
    asm volatile("ld.global.v8.b32 {%0,%1,%2,%3,%4,%5,%6,%7}, [%8];"
        : "=r"(r[0]), "=r"(r[1]), "=r"(r[2]), "=r"(r[3]),
          "=r"(r[4]), "=r"(r[5]), "=r"(r[6]), "=r"(r[7])
        : "l"(p));
}

__device__ __forceinline__ void stg256cs(float4* p, const uint32_t r[8]) {
    asm volatile("st.global.cs.v8.b32 [%0], {%1,%2,%3,%4,%5,%6,%7,%8};"
        :: "l"(p),
           "r"(r[0]), "r"(r[1]), "r"(r[2]), "r"(r[3]),
           "r"(r[4]), "r"(r[5]), "r"(r[6]), "r"(r[7])
        : "memory");
}

__global__ void __launch_bounds__(THREADS, 8)
beam_reorder_append_kernel(const float4* __restrict__ kb,
                           const float4* __restrict__ vb,
                           const float4* __restrict__ kn,
                           const float4* __restrict__ vn,
                           const int*    __restrict__ beam,
                           const int*    __restrict__ posp,
                           float4*       __restrict__ out)
{
    const unsigned base = blockIdx.x * CHUNK;             // 1024-aligned
    const bool is_v = base >= NEL4;                       // uniform per block
    const unsigned jbase = base & (NEL4 - 1);

    const int pos = *posp;                                // L1-hit, uniform
    const unsigned g = (jbase >> 14) & 127;               // uniform per block
    const unsigned delta = ((unsigned)(beam[g] - (int)g)) << 14;  // uniform

    const float4* __restrict__ buf  = is_v ? vb : kb;
    const float4* __restrict__ nbuf = is_v ? vn : kn;

    uint32_t r[V8_PER_THREAD][8];

    // Front-batch both 256-bit loads (64B/thread in flight).
    #pragma unroll
    for (int k = 0; k < V8_PER_THREAD; k++) {
        // v8 unit index within chunk: threadIdx.x + k*256; float4 j = 2*that.
        const unsigned j = jbase + 2u * (threadIdx.x + (unsigned)k * THREADS);
        const unsigned t = (j >> 4) & 127;                // same t for j, j+1
        const bool app = (t == (unsigned)pos);
        const unsigned sidx = app ? (((j >> 11) << 4) | (j & 15))
                                  : (j + delta);          // even -> 32B aligned
        const float4* __restrict__ src = app ? nbuf : buf;
        ldg256(src + sidx, r[k]);
    }

    // Streaming 256-bit stores: output never re-read.
    #pragma unroll
    for (int k = 0; k < V8_PER_THREAD; k++) {
        const unsigned o = base + 2u * (threadIdx.x + (unsigned)k * THREADS);
        stg256cs(out + o, r[k]);
    }
}

extern "C" void kernel_launch(void* const* d_in, const int* in_sizes, int n_in,
                              void* d_out, int out_size)
{
    const float4* kb   = (const float4*)d_in[0];  // k_buf  [L,G,NH,T,HD] fp32
    const float4* vb   = (const float4*)d_in[1];  // v_buf
    const float4* kn   = (const float4*)d_in[2];  // k_new  [L,G,NH,1,HD]
    const float4* vn   = (const float4*)d_in[3];  // v_new
    const int*    beam = (const int*)d_in[4];     // new_beam_idx [G]
    const int*    posp = (const int*)d_in[5];     // pos (scalar, device-side)
    float4*       out  = (float4*)d_out;          // [2,L,G,NH,T,HD] fp32

    const unsigned blocks = TOTAL / CHUNK;                // 32768
    beam_reorder_append_kernel<<<blocks, THREADS>>>(
        kb, vb, kn, vn, beam, posp, out);
}